// round 2
// baseline (speedup 1.0000x reference)
#include <cuda_runtime.h>
#include <cooperative_groups.h>
#include <math.h>

namespace cg = cooperative_groups;

#define N_NODES 384
#define H 256
#define Z 128
#define ED 128
#define AH 64
#define H4 1024
#define NE (N_NODES * N_NODES)

// ------------------------- scratch (device globals) -------------------------
__device__ float g_nodes[N_NODES * H];     // [384,256]
__device__ float g_Amat[N_NODES * H4];     // nodes@W1a + eg_b1   [384,1024]
__device__ float g_Bmat[N_NODES * H4];     // nodes@W1b           [384,1024]
__device__ float g_M[H4 * ED];             // eg_W2 @ [a0W1e | a1W1e] [1024,128]
__device__ float g_cbias[ED];              // eg_b2@[a0W1e|a1W1e] + [a0b1|a1b1]
__device__ float g_Xc0[N_NODES * AH];      // nodes @ a0W1x  [384,64]
__device__ float g_hid[(size_t)NE * ED];   // per-pair attention hidden, [s][d][128]
__device__ float g_Att0T[NE];              // attention matrix layer0, [d][s]
__device__ float g_agg0[N_NODES * H];
__device__ float g_x1[N_NODES * H];
__device__ float g_Xc1[N_NODES * AH];      // x1 @ a1W1x
__device__ float g_w[N_NODES];             // row sums of Att1

// ------------------------------- GRU kernel ---------------------------------
// 8-CTA cluster; CTA c owns h-indices [32c, 32c+32) -> 96 Whh rows in smem.
#define GRU_CTAS 8
#define GRU_HPC (H / GRU_CTAS)     // 32
#define GRU_ROWS (3 * GRU_HPC)     // 96
#define WS_LD 260                  // row stride (floats): 16B-aligned, conflict-free
#define GRU_SMEM ((GRU_ROWS * WS_LD + 2 * H + 3 * GRU_ROWS) * 4)

__global__ void __cluster_dims__(GRU_CTAS, 1, 1)
gru_kernel(const float* __restrict__ z, const float* __restrict__ Wih,
           const float* __restrict__ Whh, const float* __restrict__ bih,
           const float* __restrict__ bhh) {
  extern __shared__ float smem[];
  cg::cluster_group cluster = cg::this_cluster();
  const int c = cluster.block_rank();
  const int tid = threadIdx.x;

  float* ws = smem;                        // [96][WS_LD]
  float* hbuf = ws + GRU_ROWS * WS_LD;     // [2][256]
  float* partial = hbuf + 2 * H;           // [96]
  float* gi = partial + GRU_ROWS;          // [96]
  float* bh = gi + GRU_ROWS;               // [96]

  // load Whh slice: row r (r<96): gate g=r/32, idx i=r%32 -> global row g*256+32c+i
  for (int idx = tid; idx < GRU_ROWS * H; idx += blockDim.x) {
    int r = idx / H, k = idx % H;
    int g = r / GRU_HPC, i = r % GRU_HPC;
    int grow = g * H + c * GRU_HPC + i;
    ws[r * WS_LD + k] = Whh[grow * H + k];
  }
  // gi = Wih@z + bih (per-row), bh = bhh slice
  for (int r = tid; r < GRU_ROWS; r += blockDim.x) {
    int g = r / GRU_HPC, i = r % GRU_HPC;
    int grow = g * H + c * GRU_HPC + i;
    float s = bih[grow];
    for (int k = 0; k < Z; k++) s += Wih[grow * Z + k] * z[k];
    gi[r] = s;
    bh[r] = bhh[grow];
  }
  for (int k = tid; k < H; k += blockDim.x) hbuf[k] = 0.f;
  __syncthreads();
  cluster.sync();

  for (int step = 0; step < N_NODES; step++) {
    const int cur = step & 1, nxt = cur ^ 1;
    const float* h = hbuf + cur * H;
    if (tid < GRU_ROWS) {
      const float4* wrow = (const float4*)(ws + tid * WS_LD);
      const float4* hv = (const float4*)h;
      float s = 0.f;
#pragma unroll 8
      for (int k4 = 0; k4 < H / 4; k4++) {
        float4 wv = wrow[k4];
        float4 hh = hv[k4];
        s += wv.x * hh.x + wv.y * hh.y + wv.z * hh.z + wv.w * hh.w;
      }
      partial[tid] = s + bh[tid];
    }
    __syncthreads();
    if (tid < GRU_HPC) {
      const int i = tid;
      float ghr = partial[i];
      float ghz = partial[GRU_HPC + i];
      float ghn = partial[2 * GRU_HPC + i];
      float r = 1.f / (1.f + expf(-(gi[i] + ghr)));
      float u = 1.f / (1.f + expf(-(gi[GRU_HPC + i] + ghz)));
      float n = tanhf(gi[2 * GRU_HPC + i] + r * ghn);
      float h2 = (1.f - u) * n + u * h[c * GRU_HPC + i];
      g_nodes[step * H + c * GRU_HPC + i] = h2;
      // broadcast to every CTA's next h buffer (incl. self)
      for (int rk = 0; rk < GRU_CTAS; rk++) {
        float* remote = cluster.map_shared_rank(hbuf, rk);
        remote[nxt * H + c * GRU_HPC + i] = h2;
      }
    }
    cluster.sync();
  }
}

// --------------------------- generic fp32 GEMM ------------------------------
// C[M,N] = act(A[M,K](lda) * B[K,N](ldb) + bias), M,N mult of 64, K mult of 16.
template <bool RELU>
__global__ void gemm_kernel(int M, int N, int K, const float* __restrict__ A,
                            int lda, const float* __restrict__ B, int ldb,
                            const float* __restrict__ bias,
                            float* __restrict__ C, int ldc) {
  __shared__ float As[16][68];
  __shared__ float Bs[16][68];
  const int tx = threadIdx.x % 16, ty = threadIdx.x / 16;
  const int m0 = blockIdx.y * 64, n0 = blockIdx.x * 64;
  float acc[4][4] = {};
  for (int k0 = 0; k0 < K; k0 += 16) {
    for (int idx = threadIdx.x; idx < 64 * 16; idx += 256) {
      int m = idx / 16, k = idx % 16;
      As[k][m] = A[(size_t)(m0 + m) * lda + k0 + k];
    }
    for (int idx = threadIdx.x; idx < 16 * 64; idx += 256) {
      int k = idx / 64, n = idx % 64;
      Bs[k][n] = B[(size_t)(k0 + k) * ldb + n0 + n];
    }
    __syncthreads();
#pragma unroll
    for (int k = 0; k < 16; k++) {
      float a[4], b[4];
#pragma unroll
      for (int i = 0; i < 4; i++) a[i] = As[k][ty * 4 + i];
#pragma unroll
      for (int j = 0; j < 4; j++) b[j] = Bs[k][tx * 4 + j];
#pragma unroll
      for (int i = 0; i < 4; i++)
#pragma unroll
        for (int j = 0; j < 4; j++) acc[i][j] += a[i] * b[j];
    }
    __syncthreads();
  }
#pragma unroll
  for (int i = 0; i < 4; i++) {
#pragma unroll
    for (int j = 0; j < 4; j++) {
      float v = acc[i][j] + (bias ? bias[n0 + tx * 4 + j] : 0.f);
      if (RELU) v = fmaxf(v, 0.f);
      C[(size_t)(m0 + ty * 4 + i) * ldc + n0 + tx * 4 + j] = v;
    }
  }
}

// ------------------------------ cbias kernel --------------------------------
__global__ void cbias_kernel(const float* __restrict__ egb2,
                             const float* __restrict__ a0W1,
                             const float* __restrict__ a0b1,
                             const float* __restrict__ a1W1,
                             const float* __restrict__ a1b1) {
  int cidx = threadIdx.x;  // 128
  float s;
  if (cidx < AH) {
    s = a0b1[cidx];
    for (int k = 0; k < ED; k++) s += egb2[k] * a0W1[k * AH + cidx];
  } else {
    int cc = cidx - AH;
    s = a1b1[cc];
    for (int k = 0; k < ED; k++) s += egb2[k] * a1W1[k * AH + cc];
  }
  g_cbias[cidx] = s;
}

// ------------------------ fused edge-hidden GEMM ----------------------------
// hid[s][d][c] = relu(A[s]+B[d]) @ M[:,c] + cbias[c]
// block = 8 s-rows x 8 d-cols x 128 channels, 256 threads (8 warps).
// Warp eg owns s-row (s0+eg). Lane l: dgrp = l&3 -> d in {dgrp, dgrp+4};
// chgrp = l>>2 -> channels {chgrp*4 + 32*q + 0..3, q=0..3}.
// t = relu(a+b) computed 2x per k, reused across 16 FMAs -> 94% fma efficiency.
// Ms LDS.128 pattern: lane-groups hit byte offsets 0,16,...,112 (+128*q):
// banks 0-3,4-7,...,28-31 -> conflict-free with 4-lane broadcast.
__global__ void edge_kernel() {
  __shared__ float As[16][8];
  __shared__ float Bs[16][8];
  __shared__ float Ms[16][128];
  const int s0 = blockIdx.y * 8, d0 = blockIdx.x * 8;
  const int tid = threadIdx.x;
  const int eg = tid >> 5;           // warp id = s-index in tile
  const int lane = tid & 31;
  const int dgrp = lane & 3;         // d0+dgrp and d0+dgrp+4
  const int chb = (lane >> 2) * 4;   // channel base within each 32-chunk
  float acc0[4][4] = {};             // [q][4ch] for d = d0+dgrp
  float acc1[4][4] = {};             // [q][4ch] for d = d0+dgrp+4
  for (int k0 = 0; k0 < H4; k0 += 16) {
    if (tid < 128) {
      int kk = tid >> 3, si = tid & 7;
      As[kk][si] = g_Amat[(size_t)(s0 + si) * H4 + k0 + kk];
    } else {
      int t = tid - 128;
      int kk = t >> 3, dj = t & 7;
      Bs[kk][dj] = g_Bmat[(size_t)(d0 + dj) * H4 + k0 + kk];
    }
    for (int idx = tid; idx < 16 * 128; idx += 256) {
      int kk = idx >> 7, cc = idx & 127;
      Ms[kk][cc] = g_M[(size_t)(k0 + kk) * ED + cc];
    }
    __syncthreads();
#pragma unroll
    for (int kk = 0; kk < 16; kk++) {
      const float a = As[kk][eg];
      const float t0 = fmaxf(a + Bs[kk][dgrp], 0.f);
      const float t1 = fmaxf(a + Bs[kk][dgrp + 4], 0.f);
#pragma unroll
      for (int q = 0; q < 4; q++) {
        float4 m = *(const float4*)&Ms[kk][q * 32 + chb];
        acc0[q][0] += t0 * m.x; acc0[q][1] += t0 * m.y;
        acc0[q][2] += t0 * m.z; acc0[q][3] += t0 * m.w;
        acc1[q][0] += t1 * m.x; acc1[q][1] += t1 * m.y;
        acc1[q][2] += t1 * m.z; acc1[q][3] += t1 * m.w;
      }
    }
    __syncthreads();
  }
  const size_t base0 = (((size_t)(s0 + eg)) * N_NODES + (d0 + dgrp)) * ED;
  const size_t base1 = base0 + 4 * ED;  // d+4
#pragma unroll
  for (int q = 0; q < 4; q++) {
    float4 cb = *(const float4*)&g_cbias[q * 32 + chb];
    float4 o0, o1;
    o0.x = acc0[q][0] + cb.x; o0.y = acc0[q][1] + cb.y;
    o0.z = acc0[q][2] + cb.z; o0.w = acc0[q][3] + cb.w;
    o1.x = acc1[q][0] + cb.x; o1.y = acc1[q][1] + cb.y;
    o1.z = acc1[q][2] + cb.z; o1.w = acc1[q][3] + cb.w;
    *(float4*)&g_hid[base0 + q * 32 + chb] = o0;
    *(float4*)&g_hid[base1 + q * 32 + chb] = o1;
  }
}

// --------------------------- attention layer 0 ------------------------------
// Att0T[d][s] = sigmoid( relu(hid0[s,d]+Xc0[s]) . a0W2 + a0b2 ),  0 on diagonal
__global__ void att0_kernel(const float* __restrict__ a0W2,
                            const float* __restrict__ a0b2) {
  const int s = blockIdx.x;
  const int warp = threadIdx.x >> 5, lane = threadIdx.x & 31;
  __shared__ float xc[AH], w2[AH];
  if (threadIdx.x < AH) {
    xc[threadIdx.x] = g_Xc0[s * AH + threadIdx.x];
    w2[threadIdx.x] = a0W2[threadIdx.x];
  }
  __syncthreads();
  const float b2 = a0b2[0];
  for (int d = warp; d < N_NODES; d += 4) {
    float2 h2 = *(const float2*)&g_hid[(((size_t)s) * N_NODES + d) * ED + lane * 2];
    float v = fmaxf(h2.x + xc[lane * 2], 0.f) * w2[lane * 2] +
              fmaxf(h2.y + xc[lane * 2 + 1], 0.f) * w2[lane * 2 + 1];
    for (int o = 16; o > 0; o >>= 1) v += __shfl_down_sync(0xffffffffu, v, o);
    if (lane == 0) {
      float att = (d == s) ? 0.f : 1.f / (1.f + expf(-(v + b2)));
      g_Att0T[(size_t)d * N_NODES + s] = att;
    }
  }
}

// ------------------ attention layer 1 row-sums w[s] -------------------------
__global__ void att1w_kernel(const float* __restrict__ a1W2,
                             const float* __restrict__ a1b2) {
  const int s = blockIdx.x;
  const int warp = threadIdx.x >> 5, lane = threadIdx.x & 31;
  __shared__ float xc[AH], w2[AH];
  __shared__ float wsum[4];
  if (threadIdx.x < AH) {
    xc[threadIdx.x] = g_Xc1[s * AH + threadIdx.x];
    w2[threadIdx.x] = a1W2[threadIdx.x];
  }
  __syncthreads();
  const float b2 = a1b2[0];
  float accv = 0.f;
  for (int d = warp; d < N_NODES; d += 4) {
    float2 h2 =
        *(const float2*)&g_hid[(((size_t)s) * N_NODES + d) * ED + AH + lane * 2];
    float v = fmaxf(h2.x + xc[lane * 2], 0.f) * w2[lane * 2] +
              fmaxf(h2.y + xc[lane * 2 + 1], 0.f) * w2[lane * 2 + 1];
    for (int o = 16; o > 0; o >>= 1) v += __shfl_down_sync(0xffffffffu, v, o);
    if (lane == 0 && d != s) accv += 1.f / (1.f + expf(-(v + b2)));
  }
  if (lane == 0) wsum[warp] = accv;
  __syncthreads();
  if (threadIdx.x == 0) g_w[s] = wsum[0] + wsum[1] + wsum[2] + wsum[3];
}

// --------------------------- final reduction --------------------------------
// v = sum_s w[s]*x1[s]; out = v @ conv1_W + 384*conv1_b
__global__ void final_kernel(const float* __restrict__ c1W,
                             const float* __restrict__ c1b,
                             float* __restrict__ out) {
  __shared__ float v[H];
  __shared__ float wsh[N_NODES];
  const int tid = threadIdx.x;  // 256
  for (int i = tid; i < N_NODES; i += blockDim.x) wsh[i] = g_w[i];
  __syncthreads();
  float s = 0.f;
  for (int n = 0; n < N_NODES; n++) s += wsh[n] * g_x1[n * H + tid];
  v[tid] = s;
  __syncthreads();
  float o = (float)N_NODES * c1b[tid];
  for (int h = 0; h < H; h++) o += v[h] * c1W[h * H + tid];
  out[tid] = o;
}

// ------------------------------- launcher -----------------------------------
static float* sym_addr(const void* symbol) {
  void* p = nullptr;
  cudaGetSymbolAddress(&p, symbol);
  return (float*)p;
}

extern "C" void kernel_launch(void* const* d_in, const int* in_sizes, int n_in,
                              void* d_out, int out_size) {
  const float* z = (const float*)d_in[0];
  const float* Wih = (const float*)d_in[1];
  const float* Whh = (const float*)d_in[2];
  const float* bih = (const float*)d_in[3];
  const float* bhh = (const float*)d_in[4];
  const float* egW1 = (const float*)d_in[5];
  const float* egb1 = (const float*)d_in[6];
  const float* egW2 = (const float*)d_in[7];
  const float* egb2 = (const float*)d_in[8];
  const float* a0W1 = (const float*)d_in[9];
  const float* a0b1 = (const float*)d_in[10];
  const float* a0W2 = (const float*)d_in[11];
  const float* a0b2 = (const float*)d_in[12];
  const float* a1W1 = (const float*)d_in[13];
  const float* a1b1 = (const float*)d_in[14];
  const float* a1W2 = (const float*)d_in[15];
  const float* a1b2 = (const float*)d_in[16];
  const float* c0W = (const float*)d_in[17];
  const float* c0b = (const float*)d_in[18];
  const float* c1W = (const float*)d_in[19];
  const float* c1b = (const float*)d_in[20];
  float* out = (float*)d_out;

  cudaFuncSetAttribute(gru_kernel, cudaFuncAttributeMaxDynamicSharedMemorySize,
                       GRU_SMEM);

  float* nodes = sym_addr(g_nodes);
  float* Amat = sym_addr(g_Amat);
  float* Bmat = sym_addr(g_Bmat);
  float* Mmat = sym_addr(g_M);
  float* Xc0 = sym_addr(g_Xc0);
  float* Att0T = sym_addr(g_Att0T);
  float* agg0 = sym_addr(g_agg0);
  float* x1 = sym_addr(g_x1);
  float* Xc1 = sym_addr(g_Xc1);

  // 1. GRU -> nodes
  gru_kernel<<<GRU_CTAS, 128, GRU_SMEM>>>(z, Wih, Whh, bih, bhh);

  // 2. A = nodes @ W1a + eg_b1 ; B = nodes @ W1b
  gemm_kernel<false><<<dim3(H4 / 64, N_NODES / 64), 256>>>(
      N_NODES, H4, H, nodes, H, egW1, H4, egb1, Amat, H4);
  gemm_kernel<false><<<dim3(H4 / 64, N_NODES / 64), 256>>>(
      N_NODES, H4, H, nodes, H, egW1 + (size_t)H * H4, H4, nullptr, Bmat, H4);

  // 3. M = eg_W2 @ [a0W1e | a1W1e]
  gemm_kernel<false><<<dim3(1, H4 / 64), 256>>>(H4, AH, ED, egW2, ED, a0W1, AH,
                                                nullptr, Mmat, ED);
  gemm_kernel<false><<<dim3(1, H4 / 64), 256>>>(H4, AH, ED, egW2, ED, a1W1, AH,
                                                nullptr, Mmat + AH, ED);
  cbias_kernel<<<1, ED>>>(egb2, a0W1, a0b1, a1W1, a1b1);

  // 4. Xc0 = nodes @ a0W1x
  gemm_kernel<false><<<dim3(1, N_NODES / 64), 256>>>(
      N_NODES, AH, H, nodes, H, a0W1 + (size_t)ED * AH, AH, nullptr, Xc0, AH);

  // 5. big fused pairwise GEMM -> hid[s][d][0:128]
  edge_kernel<<<dim3(N_NODES / 8, N_NODES / 8), 256>>>();

  // 6. attention layer 0 -> Att0T [d][s]
  att0_kernel<<<N_NODES, 128>>>(a0W2, a0b2);

  // 7. agg0 = Att0T @ nodes ; x1 = relu(agg0 @ c0W + c0b)
  gemm_kernel<false><<<dim3(H / 64, N_NODES / 64), 256>>>(
      N_NODES, H, N_NODES, Att0T, N_NODES, nodes, H, nullptr, agg0, H);
  gemm_kernel<true><<<dim3(H / 64, N_NODES / 64), 256>>>(
      N_NODES, H, H, agg0, H, c0W, H, c0b, x1, H);

  // 8. Xc1 = x1 @ a1W1x
  gemm_kernel<false><<<dim3(1, N_NODES / 64), 256>>>(
      N_NODES, AH, H, x1, H, a1W1 + (size_t)ED * AH, AH, nullptr, Xc1, AH);

  // 9. w[s] = sum_d att1(s,d)
  att1w_kernel<<<N_NODES, 128>>>(a1W2, a1b2);

  // 10. out = (sum_s w[s] x1[s]) @ c1W + 384*c1b
  final_kernel<<<1, H>>>(c1W, c1b, out);
}

// round 3
// speedup vs baseline: 1.0112x; 1.0112x over previous
#include <cuda_runtime.h>
#include <cooperative_groups.h>
#include <math.h>
#include <stdint.h>

namespace cg = cooperative_groups;

#define N_NODES 384
#define H 256
#define Z 128
#define ED 128
#define AH 64
#define H4 1024
#define NE (N_NODES * N_NODES)

// ------------------------- scratch (device globals) -------------------------
__device__ float g_nodes[N_NODES * H];     // [384,256]
__device__ float g_Amat[N_NODES * H4];     // nodes@W1a + eg_b1   [384,1024]
__device__ float g_Bmat[N_NODES * H4];     // nodes@W1b           [384,1024]
__device__ float g_M[H4 * ED];             // eg_W2 @ [a0W1e | a1W1e] [1024,128]
__device__ float g_cbias[ED];              // eg_b2@[a0W1e|a1W1e] + [a0b1|a1b1]
__device__ float g_Xc0[N_NODES * AH];      // nodes @ a0W1x  [384,64]
__device__ float g_hid[(size_t)NE * ED];   // per-pair attention hidden, [s][d][128]
__device__ float g_Att0T[NE];              // attention matrix layer0, [d][s]
__device__ float g_agg0[N_NODES * H];
__device__ float g_x1[N_NODES * H];
__device__ float g_Xc1[N_NODES * AH];      // x1 @ a1W1x
__device__ float g_w[N_NODES];             // row sums of Att1

// ------------------------------- GRU kernel ---------------------------------
#define GRU_CTAS 8
#define GRU_HPC (H / GRU_CTAS)     // 32
#define GRU_ROWS (3 * GRU_HPC)     // 96
#define WS_LD 260
#define GRU_SMEM ((GRU_ROWS * WS_LD + 2 * H + 3 * GRU_ROWS) * 4)

__global__ void __cluster_dims__(GRU_CTAS, 1, 1)
gru_kernel(const float* __restrict__ z, const float* __restrict__ Wih,
           const float* __restrict__ Whh, const float* __restrict__ bih,
           const float* __restrict__ bhh) {
  extern __shared__ float smem[];
  cg::cluster_group cluster = cg::this_cluster();
  const int c = cluster.block_rank();
  const int tid = threadIdx.x;

  float* ws = smem;                        // [96][WS_LD]
  float* hbuf = ws + GRU_ROWS * WS_LD;     // [2][256]
  float* partial = hbuf + 2 * H;           // [96]
  float* gi = partial + GRU_ROWS;          // [96]
  float* bh = gi + GRU_ROWS;               // [96]

  for (int idx = tid; idx < GRU_ROWS * H; idx += blockDim.x) {
    int r = idx / H, k = idx % H;
    int g = r / GRU_HPC, i = r % GRU_HPC;
    int grow = g * H + c * GRU_HPC + i;
    ws[r * WS_LD + k] = Whh[grow * H + k];
  }
  for (int r = tid; r < GRU_ROWS; r += blockDim.x) {
    int g = r / GRU_HPC, i = r % GRU_HPC;
    int grow = g * H + c * GRU_HPC + i;
    float s = bih[grow];
    for (int k = 0; k < Z; k++) s += Wih[grow * Z + k] * z[k];
    gi[r] = s;
    bh[r] = bhh[grow];
  }
  for (int k = tid; k < H; k += blockDim.x) hbuf[k] = 0.f;
  __syncthreads();
  cluster.sync();

  for (int step = 0; step < N_NODES; step++) {
    const int cur = step & 1, nxt = cur ^ 1;
    const float* h = hbuf + cur * H;
    if (tid < GRU_ROWS) {
      const float4* wrow = (const float4*)(ws + tid * WS_LD);
      const float4* hv = (const float4*)h;
      float s = 0.f;
#pragma unroll 8
      for (int k4 = 0; k4 < H / 4; k4++) {
        float4 wv = wrow[k4];
        float4 hh = hv[k4];
        s += wv.x * hh.x + wv.y * hh.y + wv.z * hh.z + wv.w * hh.w;
      }
      partial[tid] = s + bh[tid];
    }
    __syncthreads();
    if (tid < GRU_HPC) {
      const int i = tid;
      float ghr = partial[i];
      float ghz = partial[GRU_HPC + i];
      float ghn = partial[2 * GRU_HPC + i];
      float r = 1.f / (1.f + expf(-(gi[i] + ghr)));
      float u = 1.f / (1.f + expf(-(gi[GRU_HPC + i] + ghz)));
      float n = tanhf(gi[2 * GRU_HPC + i] + r * ghn);
      float h2 = (1.f - u) * n + u * h[c * GRU_HPC + i];
      g_nodes[step * H + c * GRU_HPC + i] = h2;
      for (int rk = 0; rk < GRU_CTAS; rk++) {
        float* remote = cluster.map_shared_rank(hbuf, rk);
        remote[nxt * H + c * GRU_HPC + i] = h2;
      }
    }
    cluster.sync();
  }
}

// --------------------------- generic fp32 GEMM ------------------------------
template <bool RELU>
__global__ void gemm_kernel(int M, int N, int K, const float* __restrict__ A,
                            int lda, const float* __restrict__ B, int ldb,
                            const float* __restrict__ bias,
                            float* __restrict__ C, int ldc) {
  __shared__ float As[16][68];
  __shared__ float Bs[16][68];
  const int tx = threadIdx.x % 16, ty = threadIdx.x / 16;
  const int m0 = blockIdx.y * 64, n0 = blockIdx.x * 64;
  float acc[4][4] = {};
  for (int k0 = 0; k0 < K; k0 += 16) {
    for (int idx = threadIdx.x; idx < 64 * 16; idx += 256) {
      int m = idx / 16, k = idx % 16;
      As[k][m] = A[(size_t)(m0 + m) * lda + k0 + k];
    }
    for (int idx = threadIdx.x; idx < 16 * 64; idx += 256) {
      int k = idx / 64, n = idx % 64;
      Bs[k][n] = B[(size_t)(k0 + k) * ldb + n0 + n];
    }
    __syncthreads();
#pragma unroll
    for (int k = 0; k < 16; k++) {
      float a[4], b[4];
#pragma unroll
      for (int i = 0; i < 4; i++) a[i] = As[k][ty * 4 + i];
#pragma unroll
      for (int j = 0; j < 4; j++) b[j] = Bs[k][tx * 4 + j];
#pragma unroll
      for (int i = 0; i < 4; i++)
#pragma unroll
        for (int j = 0; j < 4; j++) acc[i][j] += a[i] * b[j];
    }
    __syncthreads();
  }
#pragma unroll
  for (int i = 0; i < 4; i++) {
#pragma unroll
    for (int j = 0; j < 4; j++) {
      float v = acc[i][j] + (bias ? bias[n0 + tx * 4 + j] : 0.f);
      if (RELU) v = fmaxf(v, 0.f);
      C[(size_t)(m0 + ty * 4 + i) * ldc + n0 + tx * 4 + j] = v;
    }
  }
}

// ------------------------------ cbias kernel --------------------------------
__global__ void cbias_kernel(const float* __restrict__ egb2,
                             const float* __restrict__ a0W1,
                             const float* __restrict__ a0b1,
                             const float* __restrict__ a1W1,
                             const float* __restrict__ a1b1) {
  int cidx = threadIdx.x;  // 128
  float s;
  if (cidx < AH) {
    s = a0b1[cidx];
    for (int k = 0; k < ED; k++) s += egb2[k] * a0W1[k * AH + cidx];
  } else {
    int cc = cidx - AH;
    s = a1b1[cc];
    for (int k = 0; k < ED; k++) s += egb2[k] * a1W1[k * AH + cc];
  }
  g_cbias[cidx] = s;
}

// ----------------- fused edge-hidden GEMM via tf32 mma.sync -----------------
// hid[s][d][c] = relu(A[s]+B[d]) @ M[:,c] + cbias[c]
// CTA: fixed s = blockIdx.y, d-tile of 128 (blockIdx.x in 0..2), all 128 ch.
// 8 warps, warp tile 64(d) x 32(ch). K=1024, chunk KC=16 (2 x k8).
// k-permuted SMEM layout so A/B fragments load as aligned LDS.64:
//   permuted col (within k8) = (k&3)*2 + ((k>>2)&1)  <->  frag pairs (k, k+4).

__device__ __forceinline__ uint32_t f2tf(float x) {
  uint32_t r;
  asm("cvt.rna.tf32.f32 %0, %1;" : "=r"(r) : "f"(x));
  return r;
}

__device__ __forceinline__ void mma_tf32(float& d0, float& d1, float& d2,
                                         float& d3, uint32_t a0, uint32_t a1,
                                         uint32_t a2, uint32_t a3, uint32_t b0,
                                         uint32_t b1) {
  asm volatile(
      "mma.sync.aligned.m16n8k8.row.col.f32.tf32.tf32.f32 "
      "{%0,%1,%2,%3},{%4,%5,%6,%7},{%8,%9},{%0,%1,%2,%3};"
      : "+f"(d0), "+f"(d1), "+f"(d2), "+f"(d3)
      : "r"(a0), "r"(a1), "r"(a2), "r"(a3), "r"(b0), "r"(b1));
}

#define EKC 16
#define TS_LD 20  // padded row stride (floats) -> conflict-light

__global__ void __launch_bounds__(256) edge_mma_kernel() {
  __shared__ float asv[H4];                  // A[s] row, fp32
  __shared__ uint32_t Ts[128 * TS_LD];       // T tile, tf32 bits, [d][perm k]
  __shared__ uint32_t Ms[128 * TS_LD];       // M tile, tf32 bits, [c][perm k]
  const int s = blockIdx.y;
  const int d0 = blockIdx.x * 128;
  const int tid = threadIdx.x;
  const int warp = tid >> 5, lane = tid & 31;
  const int wm = warp & 1, wn = warp >> 1;   // 2 x 4 warp grid
  const int m0w = wm * 64, n0w = wn * 32;
  const int g4 = lane >> 2, t4 = lane & 3;

  for (int i = tid; i < H4; i += 256) asv[i] = g_Amat[(size_t)s * H4 + i];
  // (sync folded into first chunk's barrier below)

  float acc[4][4][4] = {};  // [mi][ni][frag]

  for (int k0 = 0; k0 < H4; k0 += EKC) {
    __syncthreads();  // protects asv on first iter, SMEM reuse on later iters
    // stage T = relu(asv + B) -> tf32, permuted
    {
      const int kk4 = t4 * 4;
      const int h = (kk4 >> 2) & 1;           // 0 or 1
      const int base8 = (kk4 >> 3) * 8;       // 0 or 8
#pragma unroll
      for (int it = 0; it < 2; it++) {
        const int dd = it * 64 + (tid >> 2);
        float4 b = *(const float4*)&g_Bmat[(size_t)(d0 + dd) * H4 + k0 + kk4];
        const float* av = &asv[k0 + kk4];
        uint32_t* row = &Ts[dd * TS_LD + base8 + h];
        row[0] = f2tf(fmaxf(av[0] + b.x, 0.f));
        row[2] = f2tf(fmaxf(av[1] + b.y, 0.f));
        row[4] = f2tf(fmaxf(av[2] + b.z, 0.f));
        row[6] = f2tf(fmaxf(av[3] + b.w, 0.f));
      }
    }
    // stage M -> tf32, c-major permuted
#pragma unroll
    for (int i = 0; i < 8; i++) {
      const int e = i * 256 + tid;
      const int kk = e >> 7, c = e & 127;
      const int pos = (kk >> 3) * 8 + (kk & 3) * 2 + ((kk >> 2) & 1);
      Ms[c * TS_LD + pos] = f2tf(g_M[(size_t)(k0 + kk) * ED + c]);
    }
    __syncthreads();

#pragma unroll
    for (int k8 = 0; k8 < 2; k8++) {
      const int kb = k8 * 8 + t4 * 2;
      uint32_t af[4][4], bf[4][2];
#pragma unroll
      for (int mi = 0; mi < 4; mi++) {
        const int r = m0w + mi * 16 + g4;
        uint2 x = *(const uint2*)&Ts[r * TS_LD + kb];         // a0, a2
        uint2 y = *(const uint2*)&Ts[(r + 8) * TS_LD + kb];   // a1, a3
        af[mi][0] = x.x; af[mi][1] = y.x; af[mi][2] = x.y; af[mi][3] = y.y;
      }
#pragma unroll
      for (int ni = 0; ni < 4; ni++) {
        const int c = n0w + ni * 8 + g4;
        uint2 b = *(const uint2*)&Ms[c * TS_LD + kb];
        bf[ni][0] = b.x; bf[ni][1] = b.y;
      }
#pragma unroll
      for (int mi = 0; mi < 4; mi++)
#pragma unroll
        for (int ni = 0; ni < 4; ni++)
          mma_tf32(acc[mi][ni][0], acc[mi][ni][1], acc[mi][ni][2],
                   acc[mi][ni][3], af[mi][0], af[mi][1], af[mi][2], af[mi][3],
                   bf[ni][0], bf[ni][1]);
    }
  }

  // epilogue: + cbias, store
#pragma unroll
  for (int ni = 0; ni < 4; ni++) {
    const int ch = n0w + ni * 8 + t4 * 2;
    float2 cb = *(const float2*)&g_cbias[ch];
#pragma unroll
    for (int mi = 0; mi < 4; mi++) {
      const int d = d0 + m0w + mi * 16 + g4;
      float2 o0, o1;
      o0.x = acc[mi][ni][0] + cb.x;
      o0.y = acc[mi][ni][1] + cb.y;
      o1.x = acc[mi][ni][2] + cb.x;
      o1.y = acc[mi][ni][3] + cb.y;
      *(float2*)&g_hid[(((size_t)s) * N_NODES + d) * ED + ch] = o0;
      *(float2*)&g_hid[(((size_t)s) * N_NODES + d + 8) * ED + ch] = o1;
    }
  }
}

// --------------------------- attention layer 0 ------------------------------
__global__ void att0_kernel(const float* __restrict__ a0W2,
                            const float* __restrict__ a0b2) {
  const int s = blockIdx.x;
  const int warp = threadIdx.x >> 5, lane = threadIdx.x & 31;
  __shared__ float xc[AH], w2[AH];
  if (threadIdx.x < AH) {
    xc[threadIdx.x] = g_Xc0[s * AH + threadIdx.x];
    w2[threadIdx.x] = a0W2[threadIdx.x];
  }
  __syncthreads();
  const float b2 = a0b2[0];
  for (int d = warp; d < N_NODES; d += 8) {
    float2 h2 = *(const float2*)&g_hid[(((size_t)s) * N_NODES + d) * ED + lane * 2];
    float v = fmaxf(h2.x + xc[lane * 2], 0.f) * w2[lane * 2] +
              fmaxf(h2.y + xc[lane * 2 + 1], 0.f) * w2[lane * 2 + 1];
    for (int o = 16; o > 0; o >>= 1) v += __shfl_down_sync(0xffffffffu, v, o);
    if (lane == 0) {
      float att = (d == s) ? 0.f : 1.f / (1.f + expf(-(v + b2)));
      g_Att0T[(size_t)d * N_NODES + s] = att;
    }
  }
}

// ------------------ attention layer 1 row-sums w[s] -------------------------
__global__ void att1w_kernel(const float* __restrict__ a1W2,
                             const float* __restrict__ a1b2) {
  const int s = blockIdx.x;
  const int warp = threadIdx.x >> 5, lane = threadIdx.x & 31;
  __shared__ float xc[AH], w2[AH];
  __shared__ float wsum[8];
  if (threadIdx.x < AH) {
    xc[threadIdx.x] = g_Xc1[s * AH + threadIdx.x];
    w2[threadIdx.x] = a1W2[threadIdx.x];
  }
  __syncthreads();
  const float b2 = a1b2[0];
  float accv = 0.f;
  for (int d = warp; d < N_NODES; d += 8) {
    float2 h2 =
        *(const float2*)&g_hid[(((size_t)s) * N_NODES + d) * ED + AH + lane * 2];
    float v = fmaxf(h2.x + xc[lane * 2], 0.f) * w2[lane * 2] +
              fmaxf(h2.y + xc[lane * 2 + 1], 0.f) * w2[lane * 2 + 1];
    for (int o = 16; o > 0; o >>= 1) v += __shfl_down_sync(0xffffffffu, v, o);
    if (lane == 0 && d != s) accv += 1.f / (1.f + expf(-(v + b2)));
  }
  if (lane == 0) wsum[warp] = accv;
  __syncthreads();
  if (threadIdx.x == 0) {
    float t = 0.f;
    for (int i = 0; i < 8; i++) t += wsum[i];
    g_w[s] = t;
  }
}

// --------------------------- final reduction --------------------------------
__global__ void final_kernel(const float* __restrict__ c1W,
                             const float* __restrict__ c1b,
                             float* __restrict__ out) {
  __shared__ float v[H];
  __shared__ float wsh[N_NODES];
  const int tid = threadIdx.x;  // 256
  for (int i = tid; i < N_NODES; i += blockDim.x) wsh[i] = g_w[i];
  __syncthreads();
  float s = 0.f;
  for (int n = 0; n < N_NODES; n++) s += wsh[n] * g_x1[n * H + tid];
  v[tid] = s;
  __syncthreads();
  float o = (float)N_NODES * c1b[tid];
  for (int h = 0; h < H; h++) o += v[h] * c1W[h * H + tid];
  out[tid] = o;
}

// ------------------------------- launcher -----------------------------------
static float* sym_addr(const void* symbol) {
  void* p = nullptr;
  cudaGetSymbolAddress(&p, symbol);
  return (float*)p;
}

extern "C" void kernel_launch(void* const* d_in, const int* in_sizes, int n_in,
                              void* d_out, int out_size) {
  const float* z = (const float*)d_in[0];
  const float* Wih = (const float*)d_in[1];
  const float* Whh = (const float*)d_in[2];
  const float* bih = (const float*)d_in[3];
  const float* bhh = (const float*)d_in[4];
  const float* egW1 = (const float*)d_in[5];
  const float* egb1 = (const float*)d_in[6];
  const float* egW2 = (const float*)d_in[7];
  const float* egb2 = (const float*)d_in[8];
  const float* a0W1 = (const float*)d_in[9];
  const float* a0b1 = (const float*)d_in[10];
  const float* a0W2 = (const float*)d_in[11];
  const float* a0b2 = (const float*)d_in[12];
  const float* a1W1 = (const float*)d_in[13];
  const float* a1b1 = (const float*)d_in[14];
  const float* a1W2 = (const float*)d_in[15];
  const float* a1b2 = (const float*)d_in[16];
  const float* c0W = (const float*)d_in[17];
  const float* c0b = (const float*)d_in[18];
  const float* c1W = (const float*)d_in[19];
  const float* c1b = (const float*)d_in[20];
  float* out = (float*)d_out;

  cudaFuncSetAttribute(gru_kernel, cudaFuncAttributeMaxDynamicSharedMemorySize,
                       GRU_SMEM);

  float* nodes = sym_addr(g_nodes);
  float* Amat = sym_addr(g_Amat);
  float* Bmat = sym_addr(g_Bmat);
  float* Mmat = sym_addr(g_M);
  float* Xc0 = sym_addr(g_Xc0);
  float* Att0T = sym_addr(g_Att0T);
  float* agg0 = sym_addr(g_agg0);
  float* x1 = sym_addr(g_x1);
  float* Xc1 = sym_addr(g_Xc1);

  // 1. GRU -> nodes
  gru_kernel<<<GRU_CTAS, 128, GRU_SMEM>>>(z, Wih, Whh, bih, bhh);

  // 2. A = nodes @ W1a + eg_b1 ; B = nodes @ W1b
  gemm_kernel<false><<<dim3(H4 / 64, N_NODES / 64), 256>>>(
      N_NODES, H4, H, nodes, H, egW1, H4, egb1, Amat, H4);
  gemm_kernel<false><<<dim3(H4 / 64, N_NODES / 64), 256>>>(
      N_NODES, H4, H, nodes, H, egW1 + (size_t)H * H4, H4, nullptr, Bmat, H4);

  // 3. M = eg_W2 @ [a0W1e | a1W1e]
  gemm_kernel<false><<<dim3(1, H4 / 64), 256>>>(H4, AH, ED, egW2, ED, a0W1, AH,
                                                nullptr, Mmat, ED);
  gemm_kernel<false><<<dim3(1, H4 / 64), 256>>>(H4, AH, ED, egW2, ED, a1W1, AH,
                                                nullptr, Mmat + AH, ED);
  cbias_kernel<<<1, ED>>>(egb2, a0W1, a0b1, a1W1, a1b1);

  // 4. Xc0 = nodes @ a0W1x
  gemm_kernel<false><<<dim3(1, N_NODES / 64), 256>>>(
      N_NODES, AH, H, nodes, H, a0W1 + (size_t)ED * AH, AH, nullptr, Xc0, AH);

  // 5. pairwise edge-hidden GEMM (tf32 tensor cores) -> g_hid
  edge_mma_kernel<<<dim3(N_NODES / 128, N_NODES), 256>>>();

  // 6. attention layer 0 -> Att0T [d][s]
  att0_kernel<<<N_NODES, 256>>>(a0W2, a0b2);

  // 7. agg0 = Att0T @ nodes ; x1 = relu(agg0 @ c0W + c0b)
  gemm_kernel<false><<<dim3(H / 64, N_NODES / 64), 256>>>(
      N_NODES, H, N_NODES, Att0T, N_NODES, nodes, H, nullptr, agg0, H);
  gemm_kernel<true><<<dim3(H / 64, N_NODES / 64), 256>>>(
      N_NODES, H, H, agg0, H, c0W, H, c0b, x1, H);

  // 8. Xc1 = x1 @ a1W1x
  gemm_kernel<false><<<dim3(1, N_NODES / 64), 256>>>(
      N_NODES, AH, H, x1, H, a1W1 + (size_t)ED * AH, AH, nullptr, Xc1, AH);

  // 9. w[s] = sum_d att1(s,d)
  att1w_kernel<<<N_NODES, 256>>>(a1W2, a1b2);

  // 10. out = (sum_s w[s] x1[s]) @ c1W + 384*c1b
  final_kernel<<<1, H>>>(c1W, c1b, out);
}